// round 1
// baseline (speedup 1.0000x reference)
#include <cuda_runtime.h>

#define NB   2
#define SEQ  2048
#define EMB  1024
#define NH   16
#define HD   64
#define NS   (NB*SEQ)           // 4096

// Scratch (allocation-free): q/k/v in [n*H+h][s][d], ctx in [n][s][h][d]
__device__ float g_q[NB*NH*SEQ*HD];
__device__ float g_k[NB*NH*SEQ*HD];
__device__ float g_v[NB*NH*SEQ*HD];
__device__ float g_ctx[NS*EMB];

// ---------------------------------------------------------------------------
// GEMM: Y[m][e] = bias[e] + sum_k X[m][k] * W[e][k]
// X: (NS x EMB) row-major, W: (EMB x EMB) row-major.
// MODE 0: Y row-major (NS x EMB)      (output projection)
// MODE 1: Y in head layout [n*H+h][s][d]  (QKV projections)
// Block: 256 threads, 64x64 output tile, K-step 16, 4x4 per-thread tile.
// ---------------------------------------------------------------------------
template<int MODE>
__global__ __launch_bounds__(256)
void proj_kernel(const float* __restrict__ X, const float* __restrict__ W,
                 const float* __restrict__ bias, float* __restrict__ Y)
{
    __shared__ float As[16][64];   // As[k][m]  (transposed)
    __shared__ float Bs[16][64];   // Bs[k][n]

    const int tid = threadIdx.x;       // 0..255
    const int tx  = tid & 15;          // 0..15
    const int ty  = tid >> 4;          // 0..15
    const int m0  = blockIdx.y * 64;
    const int n0  = blockIdx.x * 64;

    const int lrow = tid >> 2;         // 0..63
    const int lseg = tid & 3;          // 0..3  (float4 segment within 16-wide K slab)

    float acc[4][4] = {};

    for (int k0 = 0; k0 < EMB; k0 += 16) {
        float4 av = *(const float4*)&X[(size_t)(m0 + lrow)*EMB + k0 + lseg*4];
        float4 bv = *(const float4*)&W[(size_t)(n0 + lrow)*EMB + k0 + lseg*4];
        As[lseg*4+0][lrow] = av.x; As[lseg*4+1][lrow] = av.y;
        As[lseg*4+2][lrow] = av.z; As[lseg*4+3][lrow] = av.w;
        Bs[lseg*4+0][lrow] = bv.x; Bs[lseg*4+1][lrow] = bv.y;
        Bs[lseg*4+2][lrow] = bv.z; Bs[lseg*4+3][lrow] = bv.w;
        __syncthreads();

        #pragma unroll
        for (int k = 0; k < 16; k++) {
            float4 a = *(const float4*)&As[k][ty*4];
            float4 b = *(const float4*)&Bs[k][tx*4];
            float ar[4] = {a.x, a.y, a.z, a.w};
            float br[4] = {b.x, b.y, b.z, b.w};
            #pragma unroll
            for (int i = 0; i < 4; i++)
                #pragma unroll
                for (int j = 0; j < 4; j++)
                    acc[i][j] = fmaf(ar[i], br[j], acc[i][j]);
        }
        __syncthreads();
    }

    #pragma unroll
    for (int i = 0; i < 4; i++) {
        int m = m0 + ty*4 + i;
        #pragma unroll
        for (int j = 0; j < 4; j++) {
            int e = n0 + tx*4 + j;
            float v = acc[i][j] + bias[e];
            if (MODE == 0) {
                Y[(size_t)m*EMB + e] = v;
            } else {
                int n = m / SEQ, s = m % SEQ;
                int h = e / HD,  d = e % HD;
                Y[(((size_t)(n*NH + h))*SEQ + s)*HD + d] = v;
            }
        }
    }
}

// ---------------------------------------------------------------------------
// Causal flash attention. One thread = one query row; Q-row + O accumulator in
// registers; K/V staged in 64-row smem tiles; online softmax in chunks of 8.
// grid: (SEQ/128, NB*NH), block: 128 threads.
// ---------------------------------------------------------------------------
__global__ __launch_bounds__(128)
void attn_kernel()
{
    __shared__ float Ks[64][64];
    __shared__ float Vs[64][64];

    const int bh  = blockIdx.y;                  // n*NH + h
    const int tid = threadIdx.x;                 // 0..127
    const int r   = blockIdx.x * 128 + tid;      // query position

    const float* qp = g_q + ((size_t)bh*SEQ + r)*HD;

    float Qr[64];
    #pragma unroll
    for (int k4 = 0; k4 < 16; k4++) {
        float4 v = ((const float4*)qp)[k4];
        Qr[k4*4+0] = v.x * 0.125f;   // pre-apply 1/sqrt(64)
        Qr[k4*4+1] = v.y * 0.125f;
        Qr[k4*4+2] = v.z * 0.125f;
        Qr[k4*4+3] = v.w * 0.125f;
    }

    float O[64];
    #pragma unroll
    for (int k = 0; k < 64; k++) O[k] = 0.f;
    float m = -1e30f, l = 0.f;

    const int tmax = blockIdx.x * 128 + 127;     // last query row in block

    for (int t0 = 0; t0 <= tmax; t0 += 64) {
        // cooperative load of K/V tile (64 x 64 floats each)
        const float4* kp = (const float4*)(g_k + ((size_t)bh*SEQ + t0)*HD);
        const float4* vp = (const float4*)(g_v + ((size_t)bh*SEQ + t0)*HD);
        for (int i = tid; i < 64*16; i += 128) {
            int row = i >> 4, seg = i & 15;
            ((float4*)&Ks[row][0])[seg] = kp[row*16 + seg];
            ((float4*)&Vs[row][0])[seg] = vp[row*16 + seg];
        }
        __syncthreads();

        for (int c = 0; c < 8; c++) {
            int tk0 = t0 + c*8;
            if (tk0 > r) break;                  // causal: rest of tile masked

            float sc[8];
            #pragma unroll
            for (int u = 0; u < 8; u++) {
                int t = c*8 + u;
                const float4* krow = (const float4*)&Ks[t][0];
                float s = 0.f;
                #pragma unroll
                for (int k4 = 0; k4 < 16; k4++) {
                    float4 kv = krow[k4];
                    s = fmaf(Qr[k4*4+0], kv.x, s);
                    s = fmaf(Qr[k4*4+1], kv.y, s);
                    s = fmaf(Qr[k4*4+2], kv.z, s);
                    s = fmaf(Qr[k4*4+3], kv.w, s);
                }
                sc[u] = (t0 + t <= r) ? s : -1e30f;
            }

            float mx = m;
            #pragma unroll
            for (int u = 0; u < 8; u++) mx = fmaxf(mx, sc[u]);
            float scale = __expf(m - mx);
            float p[8]; float ls = 0.f;
            #pragma unroll
            for (int u = 0; u < 8; u++) { p[u] = __expf(sc[u] - mx); ls += p[u]; }
            l = l * scale + ls;
            m = mx;

            #pragma unroll
            for (int k = 0; k < 64; k++) O[k] *= scale;

            #pragma unroll
            for (int u = 0; u < 8; u++) {
                const float4* vrow = (const float4*)&Vs[c*8 + u][0];
                float pu = p[u];
                #pragma unroll
                for (int k4 = 0; k4 < 16; k4++) {
                    float4 vv = vrow[k4];
                    O[k4*4+0] = fmaf(pu, vv.x, O[k4*4+0]);
                    O[k4*4+1] = fmaf(pu, vv.y, O[k4*4+1]);
                    O[k4*4+2] = fmaf(pu, vv.z, O[k4*4+2]);
                    O[k4*4+3] = fmaf(pu, vv.w, O[k4*4+3]);
                }
            }
        }
        __syncthreads();
    }

    // write ctx in [n][s][h][d] layout (contiguous (NS x EMB) for out-proj)
    const int n = bh / NH, h = bh % NH;
    float inv = 1.f / l;
    float4* op = (float4*)(g_ctx + (((size_t)n*SEQ + r)*NH + h)*HD);
    #pragma unroll
    for (int k4 = 0; k4 < 16; k4++) {
        float4 v;
        v.x = O[k4*4+0]*inv; v.y = O[k4*4+1]*inv;
        v.z = O[k4*4+2]*inv; v.w = O[k4*4+3]*inv;
        op[k4] = v;
    }
}

// ---------------------------------------------------------------------------
extern "C" void kernel_launch(void* const* d_in, const int* in_sizes, int n_in,
                              void* d_out, int out_size)
{
    const float* key   = (const float*)d_in[0];
    const float* value = (const float*)d_in[1];
    const float* query = (const float*)d_in[2];
    // d_in[3] = mask (int32 tril) — causal, applied analytically
    const float* Wk = (const float*)d_in[4];
    const float* bk = (const float*)d_in[5];
    const float* Wq = (const float*)d_in[6];
    const float* bq = (const float*)d_in[7];
    const float* Wv = (const float*)d_in[8];
    const float* bv = (const float*)d_in[9];
    const float* Wp = (const float*)d_in[10];
    const float* bp = (const float*)d_in[11];
    float* out = (float*)d_out;

    float *qs, *ks, *vs, *ctx;
    cudaGetSymbolAddress((void**)&qs,  g_q);
    cudaGetSymbolAddress((void**)&ks,  g_k);
    cudaGetSymbolAddress((void**)&vs,  g_v);
    cudaGetSymbolAddress((void**)&ctx, g_ctx);

    dim3 pgrid(EMB/64, NS/64);
    proj_kernel<1><<<pgrid, 256>>>(query, Wq, bq, qs);
    proj_kernel<1><<<pgrid, 256>>>(key,   Wk, bk, ks);
    proj_kernel<1><<<pgrid, 256>>>(value, Wv, bv, vs);

    dim3 agrid(SEQ/128, NB*NH);
    attn_kernel<<<agrid, 128>>>();

    proj_kernel<0><<<pgrid, 256>>>(ctx, Wp, bp, out);
}

// round 2
// speedup vs baseline: 2.7546x; 2.7546x over previous
#include <cuda_runtime.h>
#include <cuda_fp16.h>
#include <mma.h>
using namespace nvcuda;

#define NB   2
#define SEQ  2048
#define EMB  1024
#define NH   16
#define HD   64
#define NS   (NB*SEQ)           // 4096

// fp32 scratch: q/k/v in head layout [n*NH+h][s][d], ctx in [n][s][h][d] (= row-major NSxEMB)
__device__ float g_q[NB*NH*SEQ*HD];
__device__ float g_k[NB*NH*SEQ*HD];
__device__ float g_v[NB*NH*SEQ*HD];
__device__ float g_ctx[NS*EMB];

// ---------------------------------------------------------------------------
// GEMM: Y[m][e] = (bias[e] +) sum_k X[m][k] * W[e][k]
// X: (NS x EMB) fp32 row-major, W: (EMB x EMB) fp32 row-major.
// fp32 -> fp16 conversion fused into smem staging; HMMA via wmma, fp32 accum.
// Block tile 128(M) x 64(N), k-step 32, 256 threads = 8 warps, warp 32x32.
// MODE 0: Y = d_out row-major, bias folded via accumulator init.
// MODE 1: Y = head-layout fp32 scratch (bias added later in attention staging).
// ---------------------------------------------------------------------------
template<int MODE>
__global__ __launch_bounds__(256)
void proj_h(const float* __restrict__ X, const float* __restrict__ W,
            const float* __restrict__ bias, float* __restrict__ Y)
{
    __shared__ __align__(128) half  As[128][40];
    __shared__ __align__(128) half  Bs[64][40];
    __shared__ __align__(128) float BiasT[16][64];

    const int tid = threadIdx.x;
    const int w   = tid >> 5;
    const int m0  = blockIdx.y * 128;
    const int n0  = blockIdx.x * 64;
    const int wm  = (w >> 1) * 32;       // 0,32,64,96
    const int wn  = (w & 1) * 32;        // 0,32

    wmma::fragment<wmma::accumulator,16,16,16,float> acc[2][2];
    if (MODE == 0) {
        for (int i = tid; i < 16*64; i += 256)
            BiasT[i >> 6][i & 63] = bias[n0 + (i & 63)];
        __syncthreads();
        #pragma unroll
        for (int i = 0; i < 2; i++)
            #pragma unroll
            for (int j = 0; j < 2; j++)
                wmma::load_matrix_sync(acc[i][j], &BiasT[0][wn + j*16], 64, wmma::mem_row_major);
    } else {
        #pragma unroll
        for (int i = 0; i < 2; i++)
            #pragma unroll
            for (int j = 0; j < 2; j++)
                wmma::fill_fragment(acc[i][j], 0.0f);
    }

    for (int k0 = 0; k0 < EMB; k0 += 32) {
        #pragma unroll
        for (int it = 0; it < 4; it++) {          // A: 128 rows x 8 float4 segs
            int idx = tid + it*256;
            int row = idx >> 3, seg = idx & 7;
            float4 a = *(const float4*)&X[(size_t)(m0+row)*EMB + k0 + seg*4];
            As[row][seg*4+0] = __float2half_rn(a.x);
            As[row][seg*4+1] = __float2half_rn(a.y);
            As[row][seg*4+2] = __float2half_rn(a.z);
            As[row][seg*4+3] = __float2half_rn(a.w);
        }
        #pragma unroll
        for (int it = 0; it < 2; it++) {          // B: 64 rows x 8 float4 segs
            int idx = tid + it*256;
            int row = idx >> 3, seg = idx & 7;
            float4 b = *(const float4*)&W[(size_t)(n0+row)*EMB + k0 + seg*4];
            Bs[row][seg*4+0] = __float2half_rn(b.x);
            Bs[row][seg*4+1] = __float2half_rn(b.y);
            Bs[row][seg*4+2] = __float2half_rn(b.z);
            Bs[row][seg*4+3] = __float2half_rn(b.w);
        }
        __syncthreads();

        #pragma unroll
        for (int kk = 0; kk < 32; kk += 16) {
            wmma::fragment<wmma::matrix_a,16,16,16,half,wmma::row_major> af[2];
            wmma::fragment<wmma::matrix_b,16,16,16,half,wmma::col_major> bf[2];
            #pragma unroll
            for (int i = 0; i < 2; i++)
                wmma::load_matrix_sync(af[i], &As[wm + i*16][kk], 40);
            #pragma unroll
            for (int j = 0; j < 2; j++)
                wmma::load_matrix_sync(bf[j], &Bs[wn + j*16][kk], 40);
            #pragma unroll
            for (int i = 0; i < 2; i++)
                #pragma unroll
                for (int j = 0; j < 2; j++)
                    wmma::mma_sync(acc[i][j], af[i], bf[j], acc[i][j]);
        }
        __syncthreads();
    }

    #pragma unroll
    for (int i = 0; i < 2; i++) {
        int gm = m0 + wm + i*16;
        #pragma unroll
        for (int j = 0; j < 2; j++) {
            int e = n0 + wn + j*16;
            if (MODE == 0) {
                wmma::store_matrix_sync(&Y[(size_t)gm*EMB + e], acc[i][j], EMB, wmma::mem_row_major);
            } else {
                int h = e >> 6, d = e & 63;
                int nb = gm >> 11, s = gm & 2047;
                wmma::store_matrix_sync(&Y[(((size_t)(nb*NH + h))*SEQ + s)*HD + d],
                                        acc[i][j], HD, wmma::mem_row_major);
            }
        }
    }
}

// ---------------------------------------------------------------------------
// Causal flash attention, tensor cores. Block = one 64-query tile of one head.
// 256 threads = 8 warps; warp computes a 16x32 slab of the 64x64 S / O tiles.
// smem: Q/K/V/P fp16 tiles (ld 72), S/O fp32 tiles (ld 68), row stats.
// ---------------------------------------------------------------------------
__global__ __launch_bounds__(256)
void attn_h(const float* __restrict__ bq, const float* __restrict__ bk,
            const float* __restrict__ bv)
{
    extern __shared__ __align__(128) char smraw[];
    half*  Qs = (half*)smraw;              // [64][72]
    half*  Ks = Qs + 64*72;
    half*  Vs = Ks + 64*72;
    half*  Ps = Vs + 64*72;
    float* Ss = (float*)(Ps + 64*72);      // [64][68]
    float* Os = Ss + 64*68;                // [64][68]
    float* mrow = Os + 64*68;              // [64]
    float* lrow = mrow + 64;               // [64]

    const int tid = threadIdx.x;
    const int w   = tid >> 5;
    const int bh  = blockIdx.y;            // n*NH + h
    const int h   = bh & (NH-1);
    const int nb  = bh >> 4;
    const int q0  = blockIdx.x * 64;

    const int row = tid >> 2;              // 0..63
    const int qq  = tid & 3;               // 0..3
    const int c0  = qq * 16;

    #pragma unroll
    for (int c = 0; c < 16; c++) Os[row*68 + c0 + c] = 0.0f;
    if (qq == 0) { mrow[row] = -1e30f; lrow[row] = 0.0f; }

    {   // Q tile: (+bq) * 1/sqrt(64)
        const float* qp = g_q + ((size_t)bh*SEQ + q0 + row)*HD + c0;
        const float* bp = bq + h*HD + c0;
        #pragma unroll
        for (int c4 = 0; c4 < 4; c4++) {
            float4 v = *(const float4*)(qp + c4*4);
            float4 b = *(const float4*)(bp + c4*4);
            Qs[row*72 + c0 + c4*4+0] = __float2half_rn((v.x + b.x) * 0.125f);
            Qs[row*72 + c0 + c4*4+1] = __float2half_rn((v.y + b.y) * 0.125f);
            Qs[row*72 + c0 + c4*4+2] = __float2half_rn((v.z + b.z) * 0.125f);
            Qs[row*72 + c0 + c4*4+3] = __float2half_rn((v.w + b.w) * 0.125f);
        }
    }

    const int wm = (w >> 1) * 16;          // 0,16,32,48
    const int wn = (w & 1) * 32;           // 0,32

    for (int t0 = 0; t0 <= q0; t0 += 64) {
        {   // K/V tiles (+bias)
            const float* kp = g_k + ((size_t)bh*SEQ + t0 + row)*HD + c0;
            const float* vp = g_v + ((size_t)bh*SEQ + t0 + row)*HD + c0;
            const float* bkp = bk + h*HD + c0;
            const float* bvp = bv + h*HD + c0;
            #pragma unroll
            for (int c4 = 0; c4 < 4; c4++) {
                float4 kv = *(const float4*)(kp + c4*4);
                float4 vv = *(const float4*)(vp + c4*4);
                float4 kb = *(const float4*)(bkp + c4*4);
                float4 vb = *(const float4*)(bvp + c4*4);
                Ks[row*72 + c0 + c4*4+0] = __float2half_rn(kv.x + kb.x);
                Ks[row*72 + c0 + c4*4+1] = __float2half_rn(kv.y + kb.y);
                Ks[row*72 + c0 + c4*4+2] = __float2half_rn(kv.z + kb.z);
                Ks[row*72 + c0 + c4*4+3] = __float2half_rn(kv.w + kb.w);
                Vs[row*72 + c0 + c4*4+0] = __float2half_rn(vv.x + vb.x);
                Vs[row*72 + c0 + c4*4+1] = __float2half_rn(vv.y + vb.y);
                Vs[row*72 + c0 + c4*4+2] = __float2half_rn(vv.z + vb.z);
                Vs[row*72 + c0 + c4*4+3] = __float2half_rn(vv.w + vb.w);
            }
        }
        __syncthreads();

        {   // S = Q @ K^T  (scale pre-folded into Q)
            wmma::fragment<wmma::accumulator,16,16,16,float> sacc[2];
            wmma::fill_fragment(sacc[0], 0.0f);
            wmma::fill_fragment(sacc[1], 0.0f);
            #pragma unroll
            for (int kk = 0; kk < 64; kk += 16) {
                wmma::fragment<wmma::matrix_a,16,16,16,half,wmma::row_major> af;
                wmma::load_matrix_sync(af, Qs + wm*72 + kk, 72);
                #pragma unroll
                for (int j = 0; j < 2; j++) {
                    wmma::fragment<wmma::matrix_b,16,16,16,half,wmma::col_major> bf;
                    wmma::load_matrix_sync(bf, Ks + (wn + j*16)*72 + kk, 72);
                    wmma::mma_sync(sacc[j], af, bf, sacc[j]);
                }
            }
            #pragma unroll
            for (int j = 0; j < 2; j++)
                wmma::store_matrix_sync(Ss + wm*68 + wn + j*16, sacc[j], 68, wmma::mem_row_major);
        }
        __syncthreads();

        {   // online softmax over this 64-key chunk (4 threads per row)
            float mold = mrow[row];
            const int r = q0 + row;
            float s[16];
            float mloc = -1e30f;
            #pragma unroll
            for (int c = 0; c < 16; c++) {
                float x = Ss[row*68 + c0 + c];
                int t = t0 + c0 + c;
                x = (t <= r) ? x : -1e30f;
                s[c] = x;
                mloc = fmaxf(mloc, x);
            }
            mloc = fmaxf(mloc, __shfl_xor_sync(0xffffffffu, mloc, 1));
            mloc = fmaxf(mloc, __shfl_xor_sync(0xffffffffu, mloc, 2));
            float mnew = fmaxf(mold, mloc);
            float sc = __expf(mold - mnew);
            float ps = 0.0f;
            #pragma unroll
            for (int c = 0; c < 16; c++) {
                float p = __expf(s[c] - mnew);
                Ps[row*72 + c0 + c] = __float2half_rn(p);
                ps += p;
            }
            ps += __shfl_xor_sync(0xffffffffu, ps, 1);
            ps += __shfl_xor_sync(0xffffffffu, ps, 2);
            #pragma unroll
            for (int c = 0; c < 16; c++)
                Os[row*68 + c0 + c] *= sc;
            if (qq == 0) { mrow[row] = mnew; lrow[row] = lrow[row]*sc + ps; }
        }
        __syncthreads();

        {   // O += P @ V
            wmma::fragment<wmma::matrix_a,16,16,16,half,wmma::row_major> af[4];
            #pragma unroll
            for (int kk = 0; kk < 4; kk++)
                wmma::load_matrix_sync(af[kk], Ps + wm*72 + kk*16, 72);
            #pragma unroll
            for (int j = 0; j < 2; j++) {
                wmma::fragment<wmma::accumulator,16,16,16,float> oacc;
                wmma::load_matrix_sync(oacc, Os + wm*68 + wn + j*16, 68, wmma::mem_row_major);
                #pragma unroll
                for (int kk = 0; kk < 4; kk++) {
                    wmma::fragment<wmma::matrix_b,16,16,16,half,wmma::row_major> bf;
                    wmma::load_matrix_sync(bf, Vs + (kk*16)*72 + wn + j*16, 72);
                    wmma::mma_sync(oacc, af[kk], bf, oacc);
                }
                wmma::store_matrix_sync(Os + wm*68 + wn + j*16, oacc, 68, wmma::mem_row_major);
            }
        }
        __syncthreads();
    }

    {   // normalize + write ctx (fp32, [n][s][h][d] contiguous)
        float inv = 1.0f / lrow[row];
        float* cp = g_ctx + ((size_t)nb*SEQ + q0 + row)*EMB + h*HD + c0;
        #pragma unroll
        for (int c4 = 0; c4 < 4; c4++) {
            float4 o;
            o.x = Os[row*68 + c0 + c4*4+0] * inv;
            o.y = Os[row*68 + c0 + c4*4+1] * inv;
            o.z = Os[row*68 + c0 + c4*4+2] * inv;
            o.w = Os[row*68 + c0 + c4*4+3] * inv;
            *(float4*)(cp + c4*4) = o;
        }
    }
}

// ---------------------------------------------------------------------------
extern "C" void kernel_launch(void* const* d_in, const int* in_sizes, int n_in,
                              void* d_out, int out_size)
{
    const float* key   = (const float*)d_in[0];
    const float* value = (const float*)d_in[1];
    const float* query = (const float*)d_in[2];
    // d_in[3] = mask (int32 tril) — causal, applied analytically
    const float* Wk = (const float*)d_in[4];
    const float* bk = (const float*)d_in[5];
    const float* Wq = (const float*)d_in[6];
    const float* bq = (const float*)d_in[7];
    const float* Wv = (const float*)d_in[8];
    const float* bv = (const float*)d_in[9];
    const float* Wp = (const float*)d_in[10];
    const float* bp = (const float*)d_in[11];
    float* out = (float*)d_out;

    float *qs, *ks, *vs, *ctx;
    cudaGetSymbolAddress((void**)&qs,  g_q);
    cudaGetSymbolAddress((void**)&ks,  g_k);
    cudaGetSymbolAddress((void**)&vs,  g_v);
    cudaGetSymbolAddress((void**)&ctx, g_ctx);

    const int ATTN_SMEM = 4*64*72*(int)sizeof(half)
                        + 2*64*68*(int)sizeof(float) + 128*(int)sizeof(float);
    cudaFuncSetAttribute(attn_h, cudaFuncAttributeMaxDynamicSharedMemorySize, ATTN_SMEM);

    dim3 pgrid(EMB/64, NS/128);
    proj_h<1><<<pgrid, 256>>>(query, Wq, bq, qs);
    proj_h<1><<<pgrid, 256>>>(key,   Wk, bk, ks);
    proj_h<1><<<pgrid, 256>>>(value, Wv, bv, vs);

    dim3 agrid(SEQ/64, NB*NH);
    attn_h<<<agrid, 256, ATTN_SMEM>>>(bq, bk, bv);

    proj_h<0><<<pgrid, 256>>>(ctx, Wp, bp, out);
}

// round 3
// speedup vs baseline: 3.9401x; 1.4304x over previous
#include <cuda_runtime.h>
#include <cuda_fp16.h>
#include <mma.h>
#include <stdint.h>
using namespace nvcuda;

#define NB   2
#define SEQ  2048
#define EMB  1024
#define NH   16
#define HD   64
#define NS   (NB*SEQ)           // 4096

// fp32 scratch: q/k/v in head layout [n*NH+h][s][d], ctx in [n][s][h][d] (= row-major NSxEMB)
__device__ float g_q[NB*NH*SEQ*HD];
__device__ float g_k[NB*NH*SEQ*HD];
__device__ float g_v[NB*NH*SEQ*HD];
__device__ float g_ctx[NS*EMB];

// ---------------------------------------------------------------------------
// PTX helpers
// ---------------------------------------------------------------------------
__device__ __forceinline__ uint32_t sptr(const void* p) {
    return (uint32_t)__cvta_generic_to_shared(p);
}
__device__ __forceinline__ void ldsm4(uint32_t* r, const void* p) {
    uint32_t a = sptr(p);
    asm volatile("ldmatrix.sync.aligned.m8n8.x4.shared.b16 {%0,%1,%2,%3}, [%4];"
                 : "=r"(r[0]), "=r"(r[1]), "=r"(r[2]), "=r"(r[3]) : "r"(a));
}
__device__ __forceinline__ void ldsm4t(uint32_t* r, const void* p) {
    uint32_t a = sptr(p);
    asm volatile("ldmatrix.sync.aligned.m8n8.x4.trans.shared.b16 {%0,%1,%2,%3}, [%4];"
                 : "=r"(r[0]), "=r"(r[1]), "=r"(r[2]), "=r"(r[3]) : "r"(a));
}
// D = A(16x16 f16 row) * B(16x8 f16 col) + D, f32 accum
__device__ __forceinline__ void mma16816(float* c, const uint32_t* a, const uint32_t* b) {
    asm volatile("mma.sync.aligned.m16n8k16.row.col.f32.f16.f16.f32 "
                 "{%0,%1,%2,%3}, {%4,%5,%6,%7}, {%8,%9}, {%0,%1,%2,%3};"
                 : "+f"(c[0]), "+f"(c[1]), "+f"(c[2]), "+f"(c[3])
                 : "r"(a[0]), "r"(a[1]), "r"(a[2]), "r"(a[3]), "r"(b[0]), "r"(b[1]));
}

// ---------------------------------------------------------------------------
// Projection GEMM: Y[m][e] = (bias[e] +) sum_k X[m][k] * W[e][k]
// 128x128 block tile, k-step 32, double-buffered smem, 256 thr = 8 warps,
// warp tile 32x64 (2x4 wmma 16x16 frags). fp32->fp16 fused into staging.
// MODE 0: Y row-major (bias via accumulator init). MODE 1: head layout.
// ---------------------------------------------------------------------------
template<int MODE>
__global__ __launch_bounds__(256)
void proj2(const float* __restrict__ X, const float* __restrict__ W,
           const float* __restrict__ bias, float* __restrict__ Y)
{
    __shared__ __align__(128) half As[2][128*40];
    __shared__ __align__(128) half Bs[2][128*40];
    float* BiasT = (float*)As[1];   // overlaid; consumed before As[1] first written

    const int tid = threadIdx.x, w = tid >> 5;
    const int m0 = blockIdx.y * 128, n0 = blockIdx.x * 128;
    const int wm = (w >> 1) * 32, wn = (w & 1) * 64;

    wmma::fragment<wmma::accumulator,16,16,16,float> acc[2][4];
    if (MODE == 0) {
        for (int i = tid; i < 16*128; i += 256) BiasT[i] = bias[n0 + (i & 127)];
        __syncthreads();
        #pragma unroll
        for (int i = 0; i < 2; i++)
            #pragma unroll
            for (int j = 0; j < 4; j++)
                wmma::load_matrix_sync(acc[i][j], BiasT + wn + j*16, 128, wmma::mem_row_major);
    } else {
        #pragma unroll
        for (int i = 0; i < 2; i++)
            #pragma unroll
            for (int j = 0; j < 4; j++)
                wmma::fill_fragment(acc[i][j], 0.0f);
    }

    // stage 0 fill (k0 = 0)
    #pragma unroll
    for (int it = 0; it < 4; it++) {
        int idx = tid + it*256, r = idx >> 3, s2 = idx & 7;
        float4 a = *(const float4*)&X[(size_t)(m0+r)*EMB + s2*4];
        float4 b = *(const float4*)&W[(size_t)(n0+r)*EMB + s2*4];
        *(half2*)&As[0][r*40+s2*4]   = __floats2half2_rn(a.x, a.y);
        *(half2*)&As[0][r*40+s2*4+2] = __floats2half2_rn(a.z, a.w);
        *(half2*)&Bs[0][r*40+s2*4]   = __floats2half2_rn(b.x, b.y);
        *(half2*)&Bs[0][r*40+s2*4+2] = __floats2half2_rn(b.z, b.w);
    }
    __syncthreads();

    int buf = 0;
    for (int k0 = 0; k0 < EMB; k0 += 32) {
        float4 ra[4], rb[4];
        const bool nxt = (k0 + 32 < EMB);
        if (nxt) {
            #pragma unroll
            for (int it = 0; it < 4; it++) {
                int idx = tid + it*256, r = idx >> 3, s2 = idx & 7;
                ra[it] = *(const float4*)&X[(size_t)(m0+r)*EMB + k0+32 + s2*4];
                rb[it] = *(const float4*)&W[(size_t)(n0+r)*EMB + k0+32 + s2*4];
            }
        }
        #pragma unroll
        for (int kk = 0; kk < 32; kk += 16) {
            wmma::fragment<wmma::matrix_a,16,16,16,half,wmma::row_major> af[2];
            wmma::fragment<wmma::matrix_b,16,16,16,half,wmma::col_major> bf[4];
            #pragma unroll
            for (int i = 0; i < 2; i++)
                wmma::load_matrix_sync(af[i], &As[buf][(wm+i*16)*40 + kk], 40);
            #pragma unroll
            for (int j = 0; j < 4; j++)
                wmma::load_matrix_sync(bf[j], &Bs[buf][(wn+j*16)*40 + kk], 40);
            #pragma unroll
            for (int i = 0; i < 2; i++)
                #pragma unroll
                for (int j = 0; j < 4; j++)
                    wmma::mma_sync(acc[i][j], af[i], bf[j], acc[i][j]);
        }
        if (nxt) {
            #pragma unroll
            for (int it = 0; it < 4; it++) {
                int idx = tid + it*256, r = idx >> 3, s2 = idx & 7;
                *(half2*)&As[buf^1][r*40+s2*4]   = __floats2half2_rn(ra[it].x, ra[it].y);
                *(half2*)&As[buf^1][r*40+s2*4+2] = __floats2half2_rn(ra[it].z, ra[it].w);
                *(half2*)&Bs[buf^1][r*40+s2*4]   = __floats2half2_rn(rb[it].x, rb[it].y);
                *(half2*)&Bs[buf^1][r*40+s2*4+2] = __floats2half2_rn(rb[it].z, rb[it].w);
            }
        }
        __syncthreads();
        buf ^= 1;
    }

    #pragma unroll
    for (int i = 0; i < 2; i++) {
        int gm = m0 + wm + i*16;
        #pragma unroll
        for (int j = 0; j < 4; j++) {
            int e = n0 + wn + j*16;
            if (MODE == 0) {
                wmma::store_matrix_sync(&Y[(size_t)gm*EMB + e], acc[i][j], EMB, wmma::mem_row_major);
            } else {
                int hh = e >> 6, d = e & 63;
                int nb2 = gm >> 11, s = gm & 2047;
                wmma::store_matrix_sync(&Y[(((size_t)(nb2*NH + hh))*SEQ + s)*HD + d],
                                        acc[i][j], HD, wmma::mem_row_major);
            }
        }
    }
}

// ---------------------------------------------------------------------------
// Causal flash attention on raw mma.m16n8k16; S and O fully register-resident.
// Block = 64 queries of one head, 128 thr = 4 warps; warp owns 16 query rows.
// Per tile: 2 syncs, smem traffic = K/V staging + ldmatrix only.
// Fragment layout (PTX ISA): groupID g=lane>>2, tig=lane&3.
//   C (16x8): c0,c1 = (row g,   col 2*tig, +1); c2,c3 = (row g+8, col 2*tig, +1)
//   A (16x16 row): {a0a1,a2a3,a4a5,a6a7} = C-frags of col-halves [0:8),[8:16)
//   B (16x8 col): b0,b1 = (k 2*tig,+1, n g); b2,b3 = (k 2*tig+8,+9, n g)
// ---------------------------------------------------------------------------
__global__ __launch_bounds__(128)
void attn_m(const float* __restrict__ bq, const float* __restrict__ bk,
            const float* __restrict__ bv)
{
    __shared__ __align__(128) half Qs[64*72];
    __shared__ __align__(128) half Ks[64*72];
    __shared__ __align__(128) half Vs[64*72];
    __shared__ __align__(16)  float bks[64];
    __shared__ __align__(16)  float bvs[64];

    const int tid = threadIdx.x, w = tid >> 5, lane = tid & 31;
    const int bh = blockIdx.y, h = bh & (NH-1), nb = bh >> 4;
    const int q0 = ((int)gridDim.x - 1 - (int)blockIdx.x) * 64;  // big tiles first
    const int wm = w * 16;
    const int g = lane >> 2, tig = lane & 3;

    if (tid < 64) bks[tid] = bk[h*HD + tid];
    else          bvs[tid-64] = bv[h*HD + (tid-64)];

    {   // stage Q (+bias, *1/sqrt(64))
        int row = tid >> 1, cc = (tid & 1) * 32;
        const float* qp = g_q + ((size_t)bh*SEQ + q0 + row)*HD + cc;
        const float* bp = bq + h*HD + cc;
        #pragma unroll
        for (int c4 = 0; c4 < 8; c4++) {
            float4 v = *(const float4*)(qp + c4*4);
            float4 b = *(const float4*)(bp + c4*4);
            *(half2*)&Qs[row*72+cc+c4*4]   = __floats2half2_rn((v.x+b.x)*0.125f, (v.y+b.y)*0.125f);
            *(half2*)&Qs[row*72+cc+c4*4+2] = __floats2half2_rn((v.z+b.z)*0.125f, (v.w+b.w)*0.125f);
        }
    }
    __syncthreads();

    uint32_t qa[4][4];
    #pragma unroll
    for (int kk = 0; kk < 4; kk++)
        ldsm4(qa[kk], &Qs[(wm + (lane&7) + ((lane>>3)&1)*8)*72 + kk*16 + (lane>>4)*8]);

    float O[8][4];
    #pragma unroll
    for (int j = 0; j < 8; j++) { O[j][0]=0.f; O[j][1]=0.f; O[j][2]=0.f; O[j][3]=0.f; }
    float mA = -1e30f, mB = -1e30f, lA = 0.f, lB = 0.f;

    for (int t0 = 0; t0 <= q0; t0 += 64) {
        {   // stage K/V (+bias)
            int row = tid >> 1, cc = (tid & 1) * 32;
            const float* kp = g_k + ((size_t)bh*SEQ + t0 + row)*HD + cc;
            const float* vp = g_v + ((size_t)bh*SEQ + t0 + row)*HD + cc;
            #pragma unroll
            for (int c4 = 0; c4 < 8; c4++) {
                float4 kv = *(const float4*)(kp + c4*4);
                float4 vv = *(const float4*)(vp + c4*4);
                float4 kb = *(const float4*)&bks[cc + c4*4];
                float4 vb = *(const float4*)&bvs[cc + c4*4];
                *(half2*)&Ks[row*72+cc+c4*4]   = __floats2half2_rn(kv.x+kb.x, kv.y+kb.y);
                *(half2*)&Ks[row*72+cc+c4*4+2] = __floats2half2_rn(kv.z+kb.z, kv.w+kb.w);
                *(half2*)&Vs[row*72+cc+c4*4]   = __floats2half2_rn(vv.x+vb.x, vv.y+vb.y);
                *(half2*)&Vs[row*72+cc+c4*4+2] = __floats2half2_rn(vv.z+vb.z, vv.w+vb.w);
            }
        }
        __syncthreads();

        // S = Q K^T : 8 n-tiles of 16x8, f32 regs
        float S[8][4];
        #pragma unroll
        for (int j = 0; j < 8; j++) { S[j][0]=0.f; S[j][1]=0.f; S[j][2]=0.f; S[j][3]=0.f; }
        #pragma unroll
        for (int kk = 0; kk < 4; kk++) {
            #pragma unroll
            for (int jp = 0; jp < 4; jp++) {
                uint32_t kb4[4];
                // m0=(keys 2jp*8, k lo) m1=(keys 2jp*8, k hi) m2=(keys (2jp+1)*8, lo) m3=(hi)
                ldsm4(kb4, &Ks[(jp*16 + (lane>>4)*8 + (lane&7))*72 + kk*16 + ((lane>>3)&1)*8]);
                mma16816(S[2*jp],   qa[kk], kb4);
                mma16816(S[2*jp+1], qa[kk], kb4 + 2);
            }
        }

        if (t0 == q0) {   // diagonal tile: causal mask
            int rA = q0 + wm + g;
            #pragma unroll
            for (int j = 0; j < 8; j++) {
                int t = t0 + j*8 + tig*2;
                if (t     > rA)     S[j][0] = -1e30f;
                if (t + 1 > rA)     S[j][1] = -1e30f;
                if (t     > rA + 8) S[j][2] = -1e30f;
                if (t + 1 > rA + 8) S[j][3] = -1e30f;
            }
        }

        // online softmax in registers (row group = 4 lanes)
        float tA = -1e30f, tB = -1e30f;
        #pragma unroll
        for (int j = 0; j < 8; j++) {
            tA = fmaxf(tA, fmaxf(S[j][0], S[j][1]));
            tB = fmaxf(tB, fmaxf(S[j][2], S[j][3]));
        }
        tA = fmaxf(tA, __shfl_xor_sync(0xffffffffu, tA, 1));
        tA = fmaxf(tA, __shfl_xor_sync(0xffffffffu, tA, 2));
        tB = fmaxf(tB, __shfl_xor_sync(0xffffffffu, tB, 1));
        tB = fmaxf(tB, __shfl_xor_sync(0xffffffffu, tB, 2));
        float nA = fmaxf(mA, tA), nB = fmaxf(mB, tB);
        float scA = __expf(mA - nA), scB = __expf(mB - nB);
        float sA = 0.f, sB = 0.f;
        #pragma unroll
        for (int j = 0; j < 8; j++) {
            S[j][0] = __expf(S[j][0] - nA); S[j][1] = __expf(S[j][1] - nA);
            S[j][2] = __expf(S[j][2] - nB); S[j][3] = __expf(S[j][3] - nB);
            sA += S[j][0] + S[j][1];        sB += S[j][2] + S[j][3];
        }
        sA += __shfl_xor_sync(0xffffffffu, sA, 1);
        sA += __shfl_xor_sync(0xffffffffu, sA, 2);
        sB += __shfl_xor_sync(0xffffffffu, sB, 1);
        sB += __shfl_xor_sync(0xffffffffu, sB, 2);
        lA = lA*scA + sA;  lB = lB*scB + sB;
        mA = nA;           mB = nB;
        #pragma unroll
        for (int j = 0; j < 8; j++) {
            O[j][0] *= scA; O[j][1] *= scA; O[j][2] *= scB; O[j][3] *= scB;
        }

        // pack P (C-frags j=2kk,2kk+1) into A-frags for k-chunk kk
        uint32_t pa[4][4];
        #pragma unroll
        for (int kk = 0; kk < 4; kk++) {
            half2 h0 = __floats2half2_rn(S[2*kk][0],   S[2*kk][1]);
            half2 h1 = __floats2half2_rn(S[2*kk][2],   S[2*kk][3]);
            half2 h2 = __floats2half2_rn(S[2*kk+1][0], S[2*kk+1][1]);
            half2 h3 = __floats2half2_rn(S[2*kk+1][2], S[2*kk+1][3]);
            pa[kk][0] = *(uint32_t*)&h0;  pa[kk][1] = *(uint32_t*)&h1;
            pa[kk][2] = *(uint32_t*)&h2;  pa[kk][3] = *(uint32_t*)&h3;
        }

        // O += P V  (V via ldmatrix.trans: B[k][n] = V[t0+kk*16+k][j*8+n])
        #pragma unroll
        for (int kk = 0; kk < 4; kk++) {
            #pragma unroll
            for (int jp = 0; jp < 4; jp++) {
                uint32_t vb4[4];
                ldsm4t(vb4, &Vs[(kk*16 + ((lane>>3)&1)*8 + (lane&7))*72 + (2*jp + (lane>>4))*8]);
                mma16816(O[2*jp],   pa[kk], vb4);
                mma16816(O[2*jp+1], pa[kk], vb4 + 2);
            }
        }
        __syncthreads();
    }

    // normalize + write ctx [n][s][h][d]
    float iA = 1.f / lA, iB = 1.f / lB;
    int rA = q0 + wm + g;
    #pragma unroll
    for (int j = 0; j < 8; j++) {
        float2 vA = make_float2(O[j][0]*iA, O[j][1]*iA);
        float2 vB = make_float2(O[j][2]*iB, O[j][3]*iB);
        *(float2*)&g_ctx[((size_t)(nb*SEQ + rA    ))*EMB + h*HD + j*8 + tig*2] = vA;
        *(float2*)&g_ctx[((size_t)(nb*SEQ + rA + 8))*EMB + h*HD + j*8 + tig*2] = vB;
    }
}

// ---------------------------------------------------------------------------
extern "C" void kernel_launch(void* const* d_in, const int* in_sizes, int n_in,
                              void* d_out, int out_size)
{
    const float* key   = (const float*)d_in[0];
    const float* value = (const float*)d_in[1];
    const float* query = (const float*)d_in[2];
    // d_in[3] = mask (int32 tril) — causal, applied analytically
    const float* Wk = (const float*)d_in[4];
    const float* bk = (const float*)d_in[5];
    const float* Wq = (const float*)d_in[6];
    const float* bq = (const float*)d_in[7];
    const float* Wv = (const float*)d_in[8];
    const float* bv = (const float*)d_in[9];
    const float* Wp = (const float*)d_in[10];
    const float* bp = (const float*)d_in[11];
    float* out = (float*)d_out;

    float *qs, *ks, *vs, *ctx;
    cudaGetSymbolAddress((void**)&qs,  g_q);
    cudaGetSymbolAddress((void**)&ks,  g_k);
    cudaGetSymbolAddress((void**)&vs,  g_v);
    cudaGetSymbolAddress((void**)&ctx, g_ctx);

    dim3 pgrid(EMB/128, NS/128);      // (8, 32)
    proj2<1><<<pgrid, 256>>>(query, Wq, bq, qs);
    proj2<1><<<pgrid, 256>>>(key,   Wk, bk, ks);
    proj2<1><<<pgrid, 256>>>(value, Wv, bv, vs);

    dim3 agrid(SEQ/64, NB*NH);        // (32, 32)
    attn_m<<<agrid, 128>>>(bq, bk, bv);

    proj2<0><<<pgrid, 256>>>(ctx, Wp, bp, out);
}

// round 4
// speedup vs baseline: 7.3515x; 1.8658x over previous
#include <cuda_runtime.h>
#include <cuda_fp16.h>
#include <stdint.h>

#define NB   2
#define SEQ  2048
#define EMB  1024
#define NH   16
#define HD   64
#define NS   (NB*SEQ)           // 4096

// fp16 scratch (allocation-free)
__device__ half g_xq[NS*EMB];            // converted activations
__device__ half g_xk[NS*EMB];
__device__ half g_xv[NS*EMB];
__device__ half g_wq[EMB*EMB];           // converted weights
__device__ half g_wk[EMB*EMB];
__device__ half g_wv[EMB*EMB];
__device__ half g_wp[EMB*EMB];
__device__ half g_qh[NB*NH*SEQ*HD];      // head layout [n*NH+h][s][d], bias+scale folded
__device__ half g_kh[NB*NH*SEQ*HD];
__device__ half g_vh[NB*NH*SEQ*HD];
__device__ half g_ctxh[NS*EMB];          // [n][s][h][d] == row-major NSxEMB

// ---------------------------------------------------------------------------
// PTX helpers
// ---------------------------------------------------------------------------
__device__ __forceinline__ uint32_t sptr(const void* p) {
    return (uint32_t)__cvta_generic_to_shared(p);
}
__device__ __forceinline__ void cp16(const void* dst, const void* src) {
    asm volatile("cp.async.cg.shared.global [%0], [%1], 16;"
                 :: "r"(sptr(dst)), "l"(src));
}
__device__ __forceinline__ void cp_commit() { asm volatile("cp.async.commit_group;"); }
__device__ __forceinline__ void cp_wait0()  { asm volatile("cp.async.wait_group 0;"); }
__device__ __forceinline__ void ldsm4(uint32_t* r, const void* p) {
    asm volatile("ldmatrix.sync.aligned.m8n8.x4.shared.b16 {%0,%1,%2,%3}, [%4];"
                 : "=r"(r[0]), "=r"(r[1]), "=r"(r[2]), "=r"(r[3]) : "r"(sptr(p)));
}
__device__ __forceinline__ void ldsm4t(uint32_t* r, const void* p) {
    asm volatile("ldmatrix.sync.aligned.m8n8.x4.trans.shared.b16 {%0,%1,%2,%3}, [%4];"
                 : "=r"(r[0]), "=r"(r[1]), "=r"(r[2]), "=r"(r[3]) : "r"(sptr(p)));
}
__device__ __forceinline__ void mma16816(float* c, const uint32_t* a, const uint32_t* b) {
    asm volatile("mma.sync.aligned.m16n8k16.row.col.f32.f16.f16.f32 "
                 "{%0,%1,%2,%3}, {%4,%5,%6,%7}, {%8,%9}, {%0,%1,%2,%3};"
                 : "+f"(c[0]), "+f"(c[1]), "+f"(c[2]), "+f"(c[3])
                 : "r"(a[0]), "r"(a[1]), "r"(a[2]), "r"(a[3]), "r"(b[0]), "r"(b[1]));
}
__device__ __forceinline__ float ex2(float x) {
    float y; asm("ex2.approx.f32 %0, %1;" : "=f"(y) : "f"(x)); return y;
}

// ---------------------------------------------------------------------------
// fp32 -> fp16 bulk convert
// ---------------------------------------------------------------------------
__global__ __launch_bounds__(256)
void f2h(const float* __restrict__ src, half* __restrict__ dst, int n4)
{
    int i = blockIdx.x * 256 + threadIdx.x;
    if (i < n4) {
        float4 v = ((const float4*)src)[i];
        ((half2*)dst)[2*i]   = __floats2half2_rn(v.x, v.y);
        ((half2*)dst)[2*i+1] = __floats2half2_rn(v.z, v.w);
    }
}

// ---------------------------------------------------------------------------
// Projection GEMM, raw mma: Y[m][e] = (X[m][:] . W[e][:] + bias[e]) * scale
// X, W fp16; 128x128 block tile, k-step 32, cp.async double-buffered.
// 256 thr = 8 warps (4m x 2n), warp tile 32x64: mt in {0,1}, 8 n-tiles of 8.
// MODE 0: f32 row-major to d_out.  MODE 1: fp16 head layout [n*NH+h][s][d].
// ---------------------------------------------------------------------------
template<int MODE>
__global__ __launch_bounds__(256, 2)
void proj3(const half* __restrict__ X, const half* __restrict__ Wh,
           const float* __restrict__ bias, void* __restrict__ Yv, float scale)
{
    __shared__ __align__(128) half As[2][128*40];
    __shared__ __align__(128) half Bs[2][128*40];

    const int tid = threadIdx.x, w = tid >> 5, lane = tid & 31;
    const int m0 = blockIdx.y * 128, n0 = blockIdx.x * 128;
    const int wm = (w >> 1) * 32, wn = (w & 1) * 64;
    const int g = lane >> 2, tig = lane & 3;

    float acc[2][8][4];
    #pragma unroll
    for (int mt = 0; mt < 2; mt++)
        #pragma unroll
        for (int j = 0; j < 8; j++)
            #pragma unroll
            for (int r = 0; r < 4; r++) acc[mt][j][r] = 0.f;

    // stage buffer 0 (k0 = 0): 128 rows x 4 chunks of 16B each for A and B
    #pragma unroll
    for (int it = 0; it < 2; it++) {
        int idx = tid + it*256, r = idx >> 2, s = idx & 3;
        cp16(&As[0][r*40 + s*8], X  + (size_t)(m0+r)*EMB + s*8);
        cp16(&Bs[0][r*40 + s*8], Wh + (size_t)(n0+r)*EMB + s*8);
    }
    cp_commit(); cp_wait0();
    __syncthreads();

    int buf = 0;
    for (int k0 = 0; k0 < EMB; k0 += 32) {
        if (k0 + 32 < EMB) {
            #pragma unroll
            for (int it = 0; it < 2; it++) {
                int idx = tid + it*256, r = idx >> 2, s = idx & 3;
                cp16(&As[buf^1][r*40 + s*8], X  + (size_t)(m0+r)*EMB + k0+32 + s*8);
                cp16(&Bs[buf^1][r*40 + s*8], Wh + (size_t)(n0+r)*EMB + k0+32 + s*8);
            }
            cp_commit();
        }
        #pragma unroll
        for (int kk = 0; kk < 2; kk++) {
            uint32_t af[2][4];
            #pragma unroll
            for (int mt = 0; mt < 2; mt++)
                ldsm4(af[mt], &As[buf][(wm + mt*16 + (lane&7) + ((lane>>3)&1)*8)*40
                                       + kk*16 + (lane>>4)*8]);
            #pragma unroll
            for (int jp = 0; jp < 4; jp++) {
                uint32_t bb[4];
                ldsm4(bb, &Bs[buf][(wn + jp*16 + (lane>>4)*8 + (lane&7))*40
                                   + kk*16 + ((lane>>3)&1)*8]);
                #pragma unroll
                for (int mt = 0; mt < 2; mt++) {
                    mma16816(acc[mt][2*jp],   af[mt], bb);
                    mma16816(acc[mt][2*jp+1], af[mt], bb + 2);
                }
            }
        }
        cp_wait0();
        __syncthreads();
        buf ^= 1;
    }

    const int e0 = n0 + wn;
    #pragma unroll
    for (int mt = 0; mt < 2; mt++) {
        int gm = m0 + wm + mt*16 + g;
        #pragma unroll
        for (int j = 0; j < 8; j++) {
            int ec = e0 + j*8 + 2*tig;
            float2 b2 = *(const float2*)&bias[ec];
            float v0 = (acc[mt][j][0] + b2.x) * scale;
            float v1 = (acc[mt][j][1] + b2.y) * scale;
            float v2 = (acc[mt][j][2] + b2.x) * scale;
            float v3 = (acc[mt][j][3] + b2.y) * scale;
            if (MODE == 0) {
                float* Y = (float*)Yv;
                *(float2*)&Y[(size_t)gm*EMB + ec]     = make_float2(v0, v1);
                *(float2*)&Y[(size_t)(gm+8)*EMB + ec] = make_float2(v2, v3);
            } else {
                half* Y = (half*)Yv;
                int hh = ec >> 6, d = ec & 63;
                int nb2 = gm >> 11, s = gm & 2047;
                size_t base = ((size_t)(nb2*NH + hh))*SEQ;
                *(half2*)&Y[(base + s    )*HD + d] = __floats2half2_rn(v0, v1);
                *(half2*)&Y[(base + s + 8)*HD + d] = __floats2half2_rn(v2, v3);
            }
        }
    }
}

// ---------------------------------------------------------------------------
// Causal flash attention. Block = 64 queries, 2 warps; warp = 32 query rows
// (2 m-tiles) so each K/V ldmatrix feeds 4 MMAs. K/V cp.async double-buffered.
// Q pre-scaled by 0.125*log2(e) in projection -> softmax uses ex2 directly.
// S, O register-resident (mma.m16n8k16 fragment layouts, validated R3).
// ---------------------------------------------------------------------------
__global__ __launch_bounds__(64)
void attn3()
{
    __shared__ __align__(128) half Qs[64*72];
    __shared__ __align__(128) half Ks[2][64*72];
    __shared__ __align__(128) half Vs[2][64*72];

    const int tid = threadIdx.x, w = tid >> 5, lane = tid & 31;
    const int bh = blockIdx.y, h = bh & (NH-1), nb = bh >> 4;
    const int q0 = ((int)gridDim.x - 1 - (int)blockIdx.x) * 64;   // big tiles first
    const int wm = w * 32;
    const int g = lane >> 2, tig = lane & 3;

    const half* qb = g_qh + (size_t)bh*SEQ*HD;
    const half* kb = g_kh + (size_t)bh*SEQ*HD;
    const half* vb = g_vh + (size_t)bh*SEQ*HD;

    // stage Q + K/V tile 0 (pure copies: bias/scale already folded)
    #pragma unroll
    for (int it = 0; it < 8; it++) {
        int idx = tid + it*64, r = idx >> 3, s = idx & 7;
        cp16(&Qs[r*72 + s*8],    qb + (size_t)(q0+r)*HD + s*8);
        cp16(&Ks[0][r*72 + s*8], kb + (size_t)r*HD + s*8);
        cp16(&Vs[0][r*72 + s*8], vb + (size_t)r*HD + s*8);
    }
    cp_commit(); cp_wait0();
    __syncthreads();

    uint32_t qa[2][4][4];
    #pragma unroll
    for (int mt = 0; mt < 2; mt++)
        #pragma unroll
        for (int kk = 0; kk < 4; kk++)
            ldsm4(qa[mt][kk], &Qs[(wm + mt*16 + (lane&7) + ((lane>>3)&1)*8)*72
                                  + kk*16 + (lane>>4)*8]);

    float O[2][8][4];
    #pragma unroll
    for (int mt = 0; mt < 2; mt++)
        #pragma unroll
        for (int j = 0; j < 8; j++)
            #pragma unroll
            for (int r = 0; r < 4; r++) O[mt][j][r] = 0.f;
    float mS[2][2] = {{-1e30f,-1e30f},{-1e30f,-1e30f}};
    float lS[2][2] = {{0.f,0.f},{0.f,0.f}};

    int buf = 0;
    for (int t0 = 0; t0 <= q0; t0 += 64) {
        if (t0 + 64 <= q0) {   // prefetch next K/V tile
            #pragma unroll
            for (int it = 0; it < 8; it++) {
                int idx = tid + it*64, r = idx >> 3, s = idx & 7;
                cp16(&Ks[buf^1][r*72 + s*8], kb + (size_t)(t0+64+r)*HD + s*8);
                cp16(&Vs[buf^1][r*72 + s*8], vb + (size_t)(t0+64+r)*HD + s*8);
            }
            cp_commit();
        }

        // S = Q K^T (log2 domain)
        float S[2][8][4];
        #pragma unroll
        for (int mt = 0; mt < 2; mt++)
            #pragma unroll
            for (int j = 0; j < 8; j++)
                #pragma unroll
                for (int r = 0; r < 4; r++) S[mt][j][r] = 0.f;
        #pragma unroll
        for (int kk = 0; kk < 4; kk++)
            #pragma unroll
            for (int jp = 0; jp < 4; jp++) {
                uint32_t kb4[4];
                ldsm4(kb4, &Ks[buf][(jp*16 + (lane>>4)*8 + (lane&7))*72
                                    + kk*16 + ((lane>>3)&1)*8]);
                #pragma unroll
                for (int mt = 0; mt < 2; mt++) {
                    mma16816(S[mt][2*jp],   qa[mt][kk], kb4);
                    mma16816(S[mt][2*jp+1], qa[mt][kk], kb4 + 2);
                }
            }

        if (t0 == q0) {   // diagonal tile: causal mask
            #pragma unroll
            for (int mt = 0; mt < 2; mt++) {
                int rA = q0 + wm + mt*16 + g;
                #pragma unroll
                for (int j = 0; j < 8; j++) {
                    int t = t0 + j*8 + 2*tig;
                    if (t     > rA)     S[mt][j][0] = -1e30f;
                    if (t + 1 > rA)     S[mt][j][1] = -1e30f;
                    if (t     > rA + 8) S[mt][j][2] = -1e30f;
                    if (t + 1 > rA + 8) S[mt][j][3] = -1e30f;
                }
            }
        }

        // online softmax (base-2), rescale O, pack P into A-frags
        uint32_t pa[2][4][4];
        #pragma unroll
        for (int mt = 0; mt < 2; mt++) {
            float tA = -1e30f, tB = -1e30f;
            #pragma unroll
            for (int j = 0; j < 8; j++) {
                tA = fmaxf(tA, fmaxf(S[mt][j][0], S[mt][j][1]));
                tB = fmaxf(tB, fmaxf(S[mt][j][2], S[mt][j][3]));
            }
            tA = fmaxf(tA, __shfl_xor_sync(0xffffffffu, tA, 1));
            tA = fmaxf(tA, __shfl_xor_sync(0xffffffffu, tA, 2));
            tB = fmaxf(tB, __shfl_xor_sync(0xffffffffu, tB, 1));
            tB = fmaxf(tB, __shfl_xor_sync(0xffffffffu, tB, 2));
            float nA = fmaxf(mS[mt][0], tA), nB = fmaxf(mS[mt][1], tB);
            float scA = ex2(mS[mt][0] - nA), scB = ex2(mS[mt][1] - nB);
            float sA = 0.f, sB = 0.f;
            #pragma unroll
            for (int j = 0; j < 8; j++) {
                S[mt][j][0] = ex2(S[mt][j][0] - nA);
                S[mt][j][1] = ex2(S[mt][j][1] - nA);
                S[mt][j][2] = ex2(S[mt][j][2] - nB);
                S[mt][j][3] = ex2(S[mt][j][3] - nB);
                sA += S[mt][j][0] + S[mt][j][1];
                sB += S[mt][j][2] + S[mt][j][3];
            }
            sA += __shfl_xor_sync(0xffffffffu, sA, 1);
            sA += __shfl_xor_sync(0xffffffffu, sA, 2);
            sB += __shfl_xor_sync(0xffffffffu, sB, 1);
            sB += __shfl_xor_sync(0xffffffffu, sB, 2);
            lS[mt][0] = lS[mt][0]*scA + sA;  lS[mt][1] = lS[mt][1]*scB + sB;
            mS[mt][0] = nA;                  mS[mt][1] = nB;
            #pragma unroll
            for (int j = 0; j < 8; j++) {
                O[mt][j][0] *= scA; O[mt][j][1] *= scA;
                O[mt][j][2] *= scB; O[mt][j][3] *= scB;
            }
            #pragma unroll
            for (int kk = 0; kk < 4; kk++) {
                half2 h0 = __floats2half2_rn(S[mt][2*kk][0],   S[mt][2*kk][1]);
                half2 h1 = __floats2half2_rn(S[mt][2*kk][2],   S[mt][2*kk][3]);
                half2 h2 = __floats2half2_rn(S[mt][2*kk+1][0], S[mt][2*kk+1][1]);
                half2 h3 = __floats2half2_rn(S[mt][2*kk+1][2], S[mt][2*kk+1][3]);
                pa[mt][kk][0] = *(uint32_t*)&h0;  pa[mt][kk][1] = *(uint32_t*)&h1;
                pa[mt][kk][2] = *(uint32_t*)&h2;  pa[mt][kk][3] = *(uint32_t*)&h3;
            }
        }

        // O += P V
        #pragma unroll
        for (int kk = 0; kk < 4; kk++)
            #pragma unroll
            for (int jp = 0; jp < 4; jp++) {
                uint32_t vb4[4];
                ldsm4t(vb4, &Vs[buf][(kk*16 + ((lane>>3)&1)*8 + (lane&7))*72
                                     + (2*jp + (lane>>4))*8]);
                #pragma unroll
                for (int mt = 0; mt < 2; mt++) {
                    mma16816(O[mt][2*jp],   pa[mt][kk], vb4);
                    mma16816(O[mt][2*jp+1], pa[mt][kk], vb4 + 2);
                }
            }

        cp_wait0();
        __syncthreads();
        buf ^= 1;
    }

    // normalize + write ctx fp16 [n][s][h][d]
    #pragma unroll
    for (int mt = 0; mt < 2; mt++) {
        float iA = 1.f / lS[mt][0], iB = 1.f / lS[mt][1];
        int rA = q0 + wm + mt*16 + g;
        size_t rowA = ((size_t)(nb*SEQ + rA))*EMB + h*HD;
        size_t rowB = rowA + (size_t)8*EMB;
        #pragma unroll
        for (int j = 0; j < 8; j++) {
            *(half2*)&g_ctxh[rowA + j*8 + 2*tig] =
                __floats2half2_rn(O[mt][j][0]*iA, O[mt][j][1]*iA);
            *(half2*)&g_ctxh[rowB + j*8 + 2*tig] =
                __floats2half2_rn(O[mt][j][2]*iB, O[mt][j][3]*iB);
        }
    }
}

// ---------------------------------------------------------------------------
extern "C" void kernel_launch(void* const* d_in, const int* in_sizes, int n_in,
                              void* d_out, int out_size)
{
    const float* key   = (const float*)d_in[0];
    const float* value = (const float*)d_in[1];
    const float* query = (const float*)d_in[2];
    // d_in[3] = mask (int32 tril) — causal, applied analytically
    const float* Wk = (const float*)d_in[4];
    const float* bk = (const float*)d_in[5];
    const float* Wq = (const float*)d_in[6];
    const float* bq = (const float*)d_in[7];
    const float* Wv = (const float*)d_in[8];
    const float* bv = (const float*)d_in[9];
    const float* Wp = (const float*)d_in[10];
    const float* bp = (const float*)d_in[11];
    float* out = (float*)d_out;

    half *xq,*xk,*xv,*wq,*wk,*wv,*wp,*qh,*kh,*vh,*ctxh;
    cudaGetSymbolAddress((void**)&xq, g_xq);
    cudaGetSymbolAddress((void**)&xk, g_xk);
    cudaGetSymbolAddress((void**)&xv, g_xv);
    cudaGetSymbolAddress((void**)&wq, g_wq);
    cudaGetSymbolAddress((void**)&wk, g_wk);
    cudaGetSymbolAddress((void**)&wv, g_wv);
    cudaGetSymbolAddress((void**)&wp, g_wp);
    cudaGetSymbolAddress((void**)&qh, g_qh);
    cudaGetSymbolAddress((void**)&kh, g_kh);
    cudaGetSymbolAddress((void**)&vh, g_vh);
    cudaGetSymbolAddress((void**)&ctxh, g_ctxh);

    const int n4x = NS*EMB/4, n4w = EMB*EMB/4;
    f2h<<<n4x/256, 256>>>(query, xq, n4x);
    f2h<<<n4x/256, 256>>>(key,   xk, n4x);
    f2h<<<n4x/256, 256>>>(value, xv, n4x);
    f2h<<<n4w/256, 256>>>(Wq, wq, n4w);
    f2h<<<n4w/256, 256>>>(Wk, wk, n4w);
    f2h<<<n4w/256, 256>>>(Wv, wv, n4w);
    f2h<<<n4w/256, 256>>>(Wp, wp, n4w);

    const float QSCALE = 0.125f * 1.4426950408889634f;   // 1/sqrt(64) * log2(e)
    dim3 pg(EMB/128, NS/128);         // (8, 32)
    proj3<1><<<pg, 256>>>(xq, wq, bq, qh, QSCALE);
    proj3<1><<<pg, 256>>>(xk, wk, bk, kh, 1.0f);
    proj3<1><<<pg, 256>>>(xv, wv, bv, vh, 1.0f);

    dim3 ag(SEQ/64, NB*NH);           // (32, 32)
    attn3<<<ag, 64>>>();

    proj3<0><<<pg, 256>>>(ctxh, wp, bp, out, 1.0f);
}